// round 4
// baseline (speedup 1.0000x reference)
#include <cuda_runtime.h>
#include <cuda_bf16.h>

// Problem constants
#define NXg 384
#define NYg 384
#define NT  192
#define NPTS (NXg * NYg)          // 147456
#define NBLOCKS 144
#define NTHREADS 1024             // NBLOCKS*NTHREADS == NPTS (1 point / thread)
#define PITCH 512                 // row pitch in float2 elements (padded, halo rows/cols zero)
#define ROWS  (NXg + 2)           // 386
#define BUFSZ (ROWS * PITCH)      // 197632 float2
#define FRAME NPTS                // output frame stride
#define OUT_COMP (48 * NPTS)      // component stride in output

// k = (dt^2 / rho) * (1/h^2) ; gs uses dt^2/rho only
// DT=5e-9 -> DT^2=2.5e-17 ; H=1e-4 -> 1/H^2=1e8 ; RHO=1610
#define K_COEF  1.5527950310559006e-12f   // 2.5e-17 * 1e8 / 1610
#define K_SRC   1.5527950310559006e-20f   // 2.5e-17 / 1610

// Persistent state (double buffer), zeroed by the kernel at every launch.
__device__ float2 g_U0[BUFSZ];
__device__ float2 g_U1[BUFSZ];
__device__ unsigned int g_barrier_count;   // always left at 0 by a completed run
__device__ unsigned int g_barrier_gen;     // monotonically increases across launches

__device__ __forceinline__ void grid_barrier(unsigned int* lg)
{
    __syncthreads();
    if (threadIdx.x == 0) {
        const unsigned int target = *lg + 1u;
        __threadfence();                       // release: our stores visible before arrival
        unsigned int prev = atomicAdd(&g_barrier_count, 1u);
        if (prev == (unsigned)(NBLOCKS - 1)) {
            atomicExch(&g_barrier_count, 0u);  // reset BEFORE flipping gen
            __threadfence();
            atomicExch(&g_barrier_gen, target);
        } else {
            volatile unsigned int* gp = &g_barrier_gen;
            while (*gp != target) { }
        }
        __threadfence();                       // acquire
        *lg = target;
    }
    __syncthreads();
}

__device__ __forceinline__ float clipf(float v, float lo, float hi)
{
    return fminf(fmaxf(v, lo), hi);
}

__global__ void __launch_bounds__(NTHREADS, 1)
aniso_wave_kernel(const float* __restrict__ lc11,
                  const float* __restrict__ lc12,
                  const float* __restrict__ lc16,
                  const float* __restrict__ lc22,
                  const float* __restrict__ lc26,
                  const float* __restrict__ lc66,
                  const float* __restrict__ gauss,
                  const float* __restrict__ sigg,
                  float* __restrict__ out)
{
    __shared__ float s_sig[NT];

    const int tid  = threadIdx.x;
    const int gidx = blockIdx.x * NTHREADS + tid;

    if (tid < NT) s_sig[tid] = sigg[tid];

    // Zero both state buffers (halos AND interiors) for launch determinism.
    #pragma unroll
    for (int i = gidx; i < BUFSZ; i += NBLOCKS * NTHREADS) {
        g_U0[i] = make_float2(0.f, 0.f);
        g_U1[i] = make_float2(0.f, 0.f);
    }

    // Per-point coefficients: exp + clip, folded with k = hinv2*dt^2/rho.
    const float C11 = clipf(expf(lc11[gidx]), 5e10f,  2.5e11f);
    const float C22 = clipf(expf(lc22[gidx]), 5e9f,   5e10f);
    const float C12 = clipf(expf(lc12[gidx]), 5e9f,   5e10f);
    const float C16 = clipf(expf(lc16[gidx]), 0.0f,   6e10f);
    const float C26 = clipf(expf(lc26[gidx]), 0.0f,   2e10f);
    const float C66 = clipf(expf(lc66[gidx]), 5e9f,   3e10f);

    const float cA   = C11 * K_COEF;                  // d2x_x in Lux
    const float cB   = C66 * K_COEF;                  // d2y_x in Lux / d2x_y in Luy
    const float cCq  = (C12 + C66) * K_COEF * 0.25f;  // raw Dxy cross terms
    const float cD   = C16 * K_COEF;                  // d2x_y in Lux / d2x_x in Luy
    const float cD2q = C16 * K_COEF * 0.5f;           // 2*C16*0.25 * Dxy_x in Lux
    const float cE   = C26 * K_COEF;                  // d2y_y in Lux / d2y_x in Luy
    const float cE2q = C26 * K_COEF * 0.5f;           // 2*C26*0.25 * Dxy_y in Luy
    const float cF   = C22 * K_COEF;                  // d2y_y in Luy
    const float gs   = gauss[gidx] * K_SRC;           // source (y-component only)

    const int x = gidx / NYg;
    const int y = gidx - x * NYg;
    const int c = (x + 1) * PITCH + (y + 1);

    unsigned int lg = 0;
    if (tid == 0) lg = *(volatile unsigned int*)&g_barrier_gen;

    grid_barrier(&lg);   // buffers zeroed & visible

    float2* cur = g_U0;
    float2* nxt = g_U1;

    float u1x = 0.f, u1y = 0.f, u2x = 0.f, u2y = 0.f;

    for (int t = 0; t < NT; ++t) {
        // 8 neighbors of the interleaved (ux,uy) field. cg: bypass (non-coherent) L1.
        const float2 vN  = __ldcg(cur + c - PITCH);
        const float2 vS  = __ldcg(cur + c + PITCH);
        const float2 vW  = __ldcg(cur + c - 1);
        const float2 vE  = __ldcg(cur + c + 1);
        const float2 vNW = __ldcg(cur + c - PITCH - 1);
        const float2 vNE = __ldcg(cur + c - PITCH + 1);
        const float2 vSW = __ldcg(cur + c + PITCH - 1);
        const float2 vSE = __ldcg(cur + c + PITCH + 1);

        const float d2x_x = vN.x + vS.x - 2.f * u1x;
        const float d2y_x = vW.x + vE.x - 2.f * u1x;
        const float Dxy_x = (vNW.x - vNE.x) - (vSW.x - vSE.x);

        const float d2x_y = vN.y + vS.y - 2.f * u1y;
        const float d2y_y = vW.y + vE.y - 2.f * u1y;
        const float Dxy_y = (vNW.y - vNE.y) - (vSW.y - vSE.y);

        const float Lx = cA * d2x_x + cB * d2y_x + cCq * Dxy_y
                       + cD2q * Dxy_x + cD * d2x_y + cE * d2y_y;
        const float Ly = cB * d2x_y + cF * d2y_y + cCq * Dxy_x
                       + cD * d2x_x + cE * d2y_x + cE2q * Dxy_y;

        const float unx = 2.f * u1x - u2x + Lx;
        const float uny = 2.f * u1y - u2y + Ly + s_sig[t] * gs;

        __stcg(nxt + c, make_float2(unx, uny));

        if ((t & 3) == 3) {
            const int f = t >> 2;
            out[f * FRAME + gidx]            = unx;
            out[OUT_COMP + f * FRAME + gidx] = uny;
        }

        u2x = u1x; u2y = u1y;
        u1x = unx; u1y = uny;

        float2* tmp = cur; cur = nxt; nxt = tmp;

        if (t != NT - 1) grid_barrier(&lg);
    }
}

extern "C" void kernel_launch(void* const* d_in, const int* in_sizes, int n_in,
                              void* d_out, int out_size)
{
    const float* lc11  = (const float*)d_in[0];
    const float* lc12  = (const float*)d_in[1];
    const float* lc16  = (const float*)d_in[2];
    const float* lc22  = (const float*)d_in[3];
    const float* lc26  = (const float*)d_in[4];
    const float* lc66  = (const float*)d_in[5];
    const float* gauss = (const float*)d_in[6];
    const float* sig   = (const float*)d_in[7];
    float* out = (float*)d_out;

    aniso_wave_kernel<<<NBLOCKS, NTHREADS>>>(lc11, lc12, lc16, lc22, lc26, lc66,
                                             gauss, sig, out);
}

// round 5
// speedup vs baseline: 1.2327x; 1.2327x over previous
#include <cuda_runtime.h>
#include <cuda_bf16.h>

// Problem constants
#define NXg 384
#define NYg 384
#define NT  192
#define NPTS (NXg * NYg)          // 147456
#define NBLOCKS 144
#define NTHREADS 1024             // NBLOCKS*NTHREADS == NPTS (1 point / thread)
#define PITCH 512                 // row pitch in float2 elements (padded, halo rows/cols zero)
#define ROWS  (NXg + 2)           // 386
#define BUFSZ (ROWS * PITCH)      // 197632 float2
#define FRAME NPTS                // output frame stride
#define OUT_COMP (48 * NPTS)      // component stride in output

// k = (dt^2 / rho) * (1/h^2) ; gs uses dt^2/rho only
#define K_COEF  1.5527950310559006e-12f   // 2.5e-17 * 1e8 / 1610
#define K_SRC   1.5527950310559006e-20f   // 2.5e-17 / 1610

#define FLAG_STRIDE 32            // 128B per flag -> each flag in its own L2 line

// Persistent state (double buffer), zeroed by the kernel at every launch.
__device__ float2 g_U0[BUFSZ];
__device__ float2 g_U1[BUFSZ];
// Distributed barrier: one counter per block, padded to a full cache line.
// Monotonically increasing across launches; all equal at every launch boundary.
__device__ unsigned int g_flags[NBLOCKS * FLAG_STRIDE];

__device__ __forceinline__ unsigned int ld_acq(const unsigned int* p)
{
    unsigned int v;
    asm volatile("ld.acquire.gpu.global.u32 %0, [%1];" : "=r"(v) : "l"(p) : "memory");
    return v;
}
__device__ __forceinline__ void st_rel(unsigned int* p, unsigned int v)
{
    asm volatile("st.release.gpu.global.u32 [%0], %1;" :: "l"(p), "r"(v) : "memory");
}

// Distributed grid barrier: each block publishes its own counter; every block's
// first NBLOCKS threads poll all counters in parallel. No central serialization.
__device__ __forceinline__ void grid_barrier(unsigned int target)
{
    __syncthreads();                     // all our stores issued
    const int tid = threadIdx.x;
    if (tid == 0)
        st_rel(&g_flags[blockIdx.x * FLAG_STRIDE], target);
    if (tid < NBLOCKS) {
        const unsigned int* f = &g_flags[tid * FLAG_STRIDE];
        while (ld_acq(f) < target) { }   // monotonic -> >= compare, no reset
    }
    __syncthreads();
}

__device__ __forceinline__ float clipf(float v, float lo, float hi)
{
    return fminf(fmaxf(v, lo), hi);
}

__global__ void __launch_bounds__(NTHREADS, 1)
aniso_wave_kernel(const float* __restrict__ lc11,
                  const float* __restrict__ lc12,
                  const float* __restrict__ lc16,
                  const float* __restrict__ lc22,
                  const float* __restrict__ lc26,
                  const float* __restrict__ lc66,
                  const float* __restrict__ gauss,
                  const float* __restrict__ sigg,
                  float* __restrict__ out)
{
    __shared__ float s_sig[NT];

    const int tid  = threadIdx.x;
    const int gidx = blockIdx.x * NTHREADS + tid;

    if (tid < NT) s_sig[tid] = sigg[tid];

    // Launch-uniform barrier base (all flags equal at launch boundaries).
    const unsigned int base = ld_acq(&g_flags[blockIdx.x * FLAG_STRIDE]);

    // Zero both state buffers (halos AND interiors) for launch determinism.
    #pragma unroll
    for (int i = gidx; i < BUFSZ; i += NBLOCKS * NTHREADS) {
        g_U0[i] = make_float2(0.f, 0.f);
        g_U1[i] = make_float2(0.f, 0.f);
    }

    // Per-point coefficients: exp + clip, folded with k = hinv2*dt^2/rho.
    const float C11 = clipf(expf(lc11[gidx]), 5e10f,  2.5e11f);
    const float C22 = clipf(expf(lc22[gidx]), 5e9f,   5e10f);
    const float C12 = clipf(expf(lc12[gidx]), 5e9f,   5e10f);
    const float C16 = clipf(expf(lc16[gidx]), 0.0f,   6e10f);
    const float C26 = clipf(expf(lc26[gidx]), 0.0f,   2e10f);
    const float C66 = clipf(expf(lc66[gidx]), 5e9f,   3e10f);

    const float cA   = C11 * K_COEF;
    const float cB   = C66 * K_COEF;
    const float cCq  = (C12 + C66) * K_COEF * 0.25f;
    const float cD   = C16 * K_COEF;
    const float cD2q = C16 * K_COEF * 0.5f;
    const float cE   = C26 * K_COEF;
    const float cE2q = C26 * K_COEF * 0.5f;
    const float cF   = C22 * K_COEF;
    const float gs   = gauss[gidx] * K_SRC;

    const int x = gidx / NYg;
    const int y = gidx - x * NYg;
    const int c = (x + 1) * PITCH + (y + 1);

    grid_barrier(base + 1u);   // buffers zeroed & visible

    float2* cur = g_U0;
    float2* nxt = g_U1;

    float u1x = 0.f, u1y = 0.f, u2x = 0.f, u2y = 0.f;

    for (int t = 0; t < NT; ++t) {
        // 8 neighbors of the interleaved (ux,uy) field. cg: bypass non-coherent L1.
        const float2 vN  = __ldcg(cur + c - PITCH);
        const float2 vS  = __ldcg(cur + c + PITCH);
        const float2 vW  = __ldcg(cur + c - 1);
        const float2 vE  = __ldcg(cur + c + 1);
        const float2 vNW = __ldcg(cur + c - PITCH - 1);
        const float2 vNE = __ldcg(cur + c - PITCH + 1);
        const float2 vSW = __ldcg(cur + c + PITCH - 1);
        const float2 vSE = __ldcg(cur + c + PITCH + 1);

        const float d2x_x = vN.x + vS.x - 2.f * u1x;
        const float d2y_x = vW.x + vE.x - 2.f * u1x;
        const float Dxy_x = (vNW.x - vNE.x) - (vSW.x - vSE.x);

        const float d2x_y = vN.y + vS.y - 2.f * u1y;
        const float d2y_y = vW.y + vE.y - 2.f * u1y;
        const float Dxy_y = (vNW.y - vNE.y) - (vSW.y - vSE.y);

        const float Lx = cA * d2x_x + cB * d2y_x + cCq * Dxy_y
                       + cD2q * Dxy_x + cD * d2x_y + cE * d2y_y;
        const float Ly = cB * d2x_y + cF * d2y_y + cCq * Dxy_x
                       + cD * d2x_x + cE * d2y_x + cE2q * Dxy_y;

        const float unx = 2.f * u1x - u2x + Lx;
        const float uny = 2.f * u1y - u2y + Ly + s_sig[t] * gs;

        __stcg(nxt + c, make_float2(unx, uny));

        if ((t & 3) == 3) {
            const int f = t >> 2;
            out[f * FRAME + gidx]            = unx;
            out[OUT_COMP + f * FRAME + gidx] = uny;
        }

        u2x = u1x; u2y = u1y;
        u1x = unx; u1y = uny;

        float2* tmp = cur; cur = nxt; nxt = tmp;

        if (t != NT - 1) grid_barrier(base + (unsigned)(t + 2));
    }
}

extern "C" void kernel_launch(void* const* d_in, const int* in_sizes, int n_in,
                              void* d_out, int out_size)
{
    const float* lc11  = (const float*)d_in[0];
    const float* lc12  = (const float*)d_in[1];
    const float* lc16  = (const float*)d_in[2];
    const float* lc22  = (const float*)d_in[3];
    const float* lc26  = (const float*)d_in[4];
    const float* lc66  = (const float*)d_in[5];
    const float* gauss = (const float*)d_in[6];
    const float* sig   = (const float*)d_in[7];
    float* out = (float*)d_out;

    aniso_wave_kernel<<<NBLOCKS, NTHREADS>>>(lc11, lc12, lc16, lc22, lc26, lc66,
                                             gauss, sig, out);
}

// round 6
// speedup vs baseline: 2.0102x; 1.6307x over previous
#include <cuda_runtime.h>
#include <cuda_bf16.h>

// Problem constants
#define NXg 384
#define NYg 384
#define NT  192
#define NPTS (NXg * NYg)          // 147456
#define NBLOCKS 144               // 12x12 tiles
#define NTHREADS 512
#define TDIM 12
#define TILE 32
#define HALO 4
#define LREG 40                   // TILE + 2*HALO
#define SSTR 41                   // smem row stride (float2 units)
#define NLOC (LREG * LREG)        // 1600
#define SLOTS 4                   // 512*4 = 2048 >= 1600
#define GP 512                    // global exchange pitch (float2 units)
#define OUT_COMP (48 * NPTS)

// k = (dt^2 / rho) * (1/h^2) ; gs uses dt^2/rho only
#define K_COEF  1.5527950310559006e-12f   // 2.5e-17 * 1e8 / 1610
#define K_SRC   1.5527950310559006e-20f   // 2.5e-17 / 1610

#define FLAG_STRIDE 32            // 128B per flag -> own L2 line

// Exchange buffers: u at time T (G1) and T-1 (G2). Borders never written
// (zero from module init); tile areas fully overwritten before every read,
// so no per-launch zeroing is needed -> deterministic across graph replays.
__device__ float2 g_G1[NXg * GP];
__device__ float2 g_G2[NXg * GP];
// Distributed barrier: one counter per block, own cache line, monotonic.
__device__ unsigned int g_flags[NBLOCKS * FLAG_STRIDE];

__device__ __forceinline__ unsigned int ld_acq(const unsigned int* p)
{
    unsigned int v;
    asm volatile("ld.acquire.gpu.global.u32 %0, [%1];" : "=r"(v) : "l"(p) : "memory");
    return v;
}
__device__ __forceinline__ void st_rel(unsigned int* p, unsigned int v)
{
    asm volatile("st.release.gpu.global.u32 [%0], %1;" :: "l"(p), "r"(v) : "memory");
}

__device__ __forceinline__ void grid_barrier(unsigned int target)
{
    __syncthreads();                     // all our global stores issued
    const int tid = threadIdx.x;
    if (tid == 0) {
        __threadfence();                 // publish block's stores before flag
        st_rel(&g_flags[blockIdx.x * FLAG_STRIDE], target);
    }
    if (tid < NBLOCKS) {
        const unsigned int* f = &g_flags[tid * FLAG_STRIDE];
        while (ld_acq(f) < target) { }   // monotonic -> no reset needed
        __threadfence();                 // acquire for the whole block
    }
    __syncthreads();
}

__device__ __forceinline__ float clipf(float v, float lo, float hi)
{
    return fminf(fmaxf(v, lo), hi);
}

__global__ void __launch_bounds__(NTHREADS, 1)
aniso_wave_kernel(const float* __restrict__ lc11,
                  const float* __restrict__ lc12,
                  const float* __restrict__ lc16,
                  const float* __restrict__ lc22,
                  const float* __restrict__ lc26,
                  const float* __restrict__ lc66,
                  const float* __restrict__ gauss,
                  const float* __restrict__ sigg,
                  float* __restrict__ out)
{
    __shared__ float2 u1s[LREG * SSTR];   // current time level, whole 40x40 region
    __shared__ float  s_sig[NT];

    const int tid = threadIdx.x;
    const int tX  = blockIdx.x / TDIM;
    const int tY  = blockIdx.x - tX * TDIM;

    if (tid < NT) s_sig[tid] = sigg[tid];

    const unsigned int base = ld_acq(&g_flags[blockIdx.x * FLAG_STRIDE]);

    // Zero smem region (per launch).
    for (int i = tid; i < LREG * SSTR; i += NTHREADS)
        u1s[i] = make_float2(0.f, 0.f);

    // Per-slot (owned point) setup: fixed ownership, coefficients in registers.
    int   LXa[SLOTS], LYa[SLOTS], soff[SLOTS], goff[SLOTS], oidx[SLOTS];
    bool  dom[SLOTS];
    float cA[SLOTS], cB[SLOTS], cCq[SLOTS], cD[SLOTS], cD2q[SLOTS];
    float cE[SLOTS], cE2q[SLOTS], cF[SLOTS], gs[SLOTS];
    float u1cx[SLOTS], u1cy[SLOTS], u2x[SLOTS], u2y[SLOTS];

    #pragma unroll
    for (int s = 0; s < SLOTS; ++s) {
        const int p  = tid + s * NTHREADS;
        const int lx = p / LREG;
        const int ly = p - lx * LREG;
        const bool live = p < NLOC;
        const int gx = tX * TILE + lx - HALO;
        const int gy = tY * TILE + ly - HALO;
        const bool d = live && gx >= 0 && gx < NXg && gy >= 0 && gy < NYg;
        LXa[s] = lx; LYa[s] = ly; dom[s] = d;
        soff[s] = lx * SSTR + ly;
        const int gi = d ? gx * NYg + gy : 0;
        oidx[s] = gi;
        goff[s] = d ? gx * GP + gy : 0;
        u1cx[s] = u1cy[s] = u2x[s] = u2y[s] = 0.f;

        float C11 = 0.f, C22 = 0.f, C12 = 0.f, C16 = 0.f, C26 = 0.f, C66 = 0.f, gg = 0.f;
        if (d) {
            C11 = clipf(expf(lc11[gi]), 5e10f,  2.5e11f);
            C22 = clipf(expf(lc22[gi]), 5e9f,   5e10f);
            C12 = clipf(expf(lc12[gi]), 5e9f,   5e10f);
            C16 = clipf(expf(lc16[gi]), 0.0f,   6e10f);
            C26 = clipf(expf(lc26[gi]), 0.0f,   2e10f);
            C66 = clipf(expf(lc66[gi]), 5e9f,   3e10f);
            gg  = gauss[gi];
        }
        cA[s]   = C11 * K_COEF;
        cB[s]   = C66 * K_COEF;
        cCq[s]  = (C12 + C66) * K_COEF * 0.25f;
        cD[s]   = C16 * K_COEF;
        cD2q[s] = C16 * K_COEF * 0.5f;
        cE[s]   = C26 * K_COEF;
        cE2q[s] = C26 * K_COEF * 0.5f;
        cF[s]   = C22 * K_COEF;
        gs[s]   = gg * K_SRC;
    }
    __syncthreads();   // smem zero + sig visible

    for (int ss = 0; ss < 48; ++ss) {
        // ---- 4 local substeps (trapezoid: region [st+1, 39-st)^2) ----
        #pragma unroll
        for (int st = 0; st < 4; ++st) {
            const int t  = ss * 4 + st;
            const int lo = st + 1;
            const int hi = (LREG - 1) - st;   // 39 - st
            const float sigt = s_sig[t];

            float nx[SLOTS], ny[SLOTS];
            bool  comp[SLOTS];
            #pragma unroll
            for (int s = 0; s < SLOTS; ++s) {
                comp[s] = dom[s] && LXa[s] >= lo && LXa[s] < hi
                                 && LYa[s] >= lo && LYa[s] < hi;
                if (comp[s]) {
                    const int o = soff[s];
                    const float2 vN  = u1s[o - SSTR];
                    const float2 vS  = u1s[o + SSTR];
                    const float2 vW  = u1s[o - 1];
                    const float2 vE  = u1s[o + 1];
                    const float2 vNW = u1s[o - SSTR - 1];
                    const float2 vNE = u1s[o - SSTR + 1];
                    const float2 vSW = u1s[o + SSTR - 1];
                    const float2 vSE = u1s[o + SSTR + 1];

                    const float d2x_x = vN.x + vS.x - 2.f * u1cx[s];
                    const float d2y_x = vW.x + vE.x - 2.f * u1cx[s];
                    const float Dxy_x = (vNW.x - vNE.x) - (vSW.x - vSE.x);

                    const float d2x_y = vN.y + vS.y - 2.f * u1cy[s];
                    const float d2y_y = vW.y + vE.y - 2.f * u1cy[s];
                    const float Dxy_y = (vNW.y - vNE.y) - (vSW.y - vSE.y);

                    const float Lx = cA[s] * d2x_x + cB[s] * d2y_x + cCq[s] * Dxy_y
                                   + cD2q[s] * Dxy_x + cD[s] * d2x_y + cE[s] * d2y_y;
                    const float Ly = cB[s] * d2x_y + cF[s] * d2y_y + cCq[s] * Dxy_x
                                   + cD[s] * d2x_x + cE[s] * d2y_x + cE2q[s] * Dxy_y;

                    nx[s] = 2.f * u1cx[s] - u2x[s] + Lx;
                    ny[s] = 2.f * u1cy[s] - u2y[s] + Ly + sigt * gs[s];
                }
            }
            __syncthreads();   // all reads of old u1s done
            #pragma unroll
            for (int s = 0; s < SLOTS; ++s) {
                if (comp[s]) {
                    u2x[s]  = u1cx[s];  u2y[s]  = u1cy[s];
                    u1cx[s] = nx[s];    u1cy[s] = ny[s];
                    u1s[soff[s]] = make_float2(nx[s], ny[s]);
                }
            }
            __syncthreads();
        }

        // ---- snapshot: t = 4*ss+3 is frame ss ----
        #pragma unroll
        for (int s = 0; s < SLOTS; ++s) {
            const bool inter = LXa[s] >= HALO && LXa[s] < HALO + TILE
                            && LYa[s] >= HALO && LYa[s] < HALO + TILE;
            if (inter) {
                out[ss * NPTS + oidx[s]]            = u1cx[s];
                out[OUT_COMP + ss * NPTS + oidx[s]] = u1cy[s];
            }
        }

        // ---- halo exchange through global, one grid barrier ----
        if (ss < 47) {
            #pragma unroll
            for (int s = 0; s < SLOTS; ++s) {
                const bool inter = LXa[s] >= HALO && LXa[s] < HALO + TILE
                                && LYa[s] >= HALO && LYa[s] < HALO + TILE;
                if (inter) {
                    g_G1[goff[s]] = make_float2(u1cx[s], u1cy[s]);
                    g_G2[goff[s]] = make_float2(u2x[s], u2y[s]);
                }
            }
            grid_barrier(base + (unsigned)(ss + 1));
            #pragma unroll
            for (int s = 0; s < SLOTS; ++s) {
                const bool inter = LXa[s] >= HALO && LXa[s] < HALO + TILE
                                && LYa[s] >= HALO && LYa[s] < HALO + TILE;
                if (dom[s] && !inter) {
                    const float2 a = __ldcg(&g_G1[goff[s]]);
                    const float2 b = __ldcg(&g_G2[goff[s]]);
                    u1cx[s] = a.x; u1cy[s] = a.y;
                    u2x[s]  = b.x; u2y[s]  = b.y;
                    u1s[soff[s]] = a;
                }
            }
            __syncthreads();   // halo smem writes visible before next substep
        }
    }
}

extern "C" void kernel_launch(void* const* d_in, const int* in_sizes, int n_in,
                              void* d_out, int out_size)
{
    const float* lc11  = (const float*)d_in[0];
    const float* lc12  = (const float*)d_in[1];
    const float* lc16  = (const float*)d_in[2];
    const float* lc22  = (const float*)d_in[3];
    const float* lc26  = (const float*)d_in[4];
    const float* lc66  = (const float*)d_in[5];
    const float* gauss = (const float*)d_in[6];
    const float* sig   = (const float*)d_in[7];
    float* out = (float*)d_out;

    aniso_wave_kernel<<<NBLOCKS, NTHREADS>>>(lc11, lc12, lc16, lc22, lc26, lc66,
                                             gauss, sig, out);
}

// round 10
// speedup vs baseline: 2.2230x; 1.1059x over previous
#include <cuda_runtime.h>
#include <cuda_bf16.h>

// Problem constants
#define NXg 384
#define NYg 384
#define NT  192
#define NPTS (NXg * NYg)          // 147456
#define NBLOCKS 144               // 12x12 tiles
#define NTHREADS 896              // 28 warps; 800 active (20 row-pairs x 40 cols)
#define NACT 800
#define TDIM 12
#define TILE 32
#define HALO 4
#define LREG 40                   // TILE + 2*HALO
#define SROW 44                   // smem row stride in float2 (pads + bank phasing)
#define SMSZ (42 * SROW)          // 42 rows (1 pad each side) x 44
#define SOFF(r, c) (((r) + 1) * SROW + ((c) + 1))
#define GPitch 512
#define OUT_COMP (48 * NPTS)

// k = (dt^2 / rho) * (1/h^2) ; source uses dt^2/rho only
#define K_COEF  1.5527950310559006e-12f
#define K_SRC   1.5527950310559006e-20f

#define FLAG_STRIDE 32            // 128B per flag -> own L2 line

// Exchange buffer: (u1x,u1y,u2x,u2y) per point. Only interior-rim points are
// written (by their owner) and only halo points are read -> every read slot is
// written in the same super-step before the barrier. No zero-init needed.
__device__ float4 g_G[NXg * GPitch];
// Distributed barrier: one counter per block, own cache line, monotonic.
__device__ unsigned int g_flags[NBLOCKS * FLAG_STRIDE];

static __device__ __forceinline__ unsigned int ld_acq(const unsigned int* p)
{
    unsigned int v;
    asm volatile("ld.acquire.gpu.global.u32 %0, [%1];" : "=r"(v) : "l"(p) : "memory");
    return v;
}
static __device__ __forceinline__ void st_rel(unsigned int* p, unsigned int v)
{
    asm volatile("st.release.gpu.global.u32 [%0], %1;" :: "l"(p), "r"(v) : "memory");
}

static __device__ __forceinline__ void grid_barrier(unsigned int target)
{
    __syncthreads();                     // all our global stores issued
    const int tid = threadIdx.x;
    if (tid == 0) {
        __threadfence();                 // publish block's stores before flag
        st_rel(&g_flags[blockIdx.x * FLAG_STRIDE], target);
    }
    if (tid < NBLOCKS) {
        const unsigned int* f = &g_flags[tid * FLAG_STRIDE];
        while (ld_acq(f) < target) { }   // monotonic -> no reset needed
        __threadfence();                 // acquire for the whole block
    }
    __syncthreads();
}

// ---- packed f32x2 helpers (sm_100+) ----
static __device__ __forceinline__ float2 fadd2(float2 a, float2 b)
{
    unsigned long long ra = *reinterpret_cast<unsigned long long*>(&a);
    unsigned long long rb = *reinterpret_cast<unsigned long long*>(&b);
    unsigned long long rd;
    asm("add.rn.f32x2 %0, %1, %2;" : "=l"(rd) : "l"(ra), "l"(rb));
    float2 d; *reinterpret_cast<unsigned long long*>(&d) = rd; return d;
}
static __device__ __forceinline__ float2 fmul2(float2 a, float2 b)
{
    unsigned long long ra = *reinterpret_cast<unsigned long long*>(&a);
    unsigned long long rb = *reinterpret_cast<unsigned long long*>(&b);
    unsigned long long rd;
    asm("mul.rn.f32x2 %0, %1, %2;" : "=l"(rd) : "l"(ra), "l"(rb));
    float2 d; *reinterpret_cast<unsigned long long*>(&d) = rd; return d;
}
static __device__ __forceinline__ float2 ffma2(float2 a, float2 b, float2 c)
{
    unsigned long long ra = *reinterpret_cast<unsigned long long*>(&a);
    unsigned long long rb = *reinterpret_cast<unsigned long long*>(&b);
    unsigned long long rc = *reinterpret_cast<unsigned long long*>(&c);
    unsigned long long rd;
    asm("fma.rn.f32x2 %0, %1, %2, %3;" : "=l"(rd) : "l"(ra), "l"(rb), "l"(rc));
    float2 d; *reinterpret_cast<unsigned long long*>(&d) = rd; return d;
}

static __device__ __forceinline__ float clipf(float v, float lo, float hi)
{
    return fminf(fmaxf(v, lo), hi);
}

__global__ void __launch_bounds__(NTHREADS, 1)
aniso_wave_kernel(const float* __restrict__ lc11,
                  const float* __restrict__ lc12,
                  const float* __restrict__ lc16,
                  const float* __restrict__ lc22,
                  const float* __restrict__ lc26,
                  const float* __restrict__ lc66,
                  const float* __restrict__ gauss,
                  const float* __restrict__ sigg,
                  float* __restrict__ out)
{
    __shared__ float2 sA[SMSZ];
    __shared__ float2 sB[SMSZ];
    __shared__ float  s_sig[NT];

    const int tid = threadIdx.x;
    const int bX  = blockIdx.x / TDIM;
    const int bY  = blockIdx.x - bX * TDIM;

    if (tid < NT) s_sig[tid] = sigg[tid];

    const unsigned int base = ld_acq(&g_flags[blockIdx.x * FLAG_STRIDE]);

    for (int i = tid; i < SMSZ; i += NTHREADS) {
        sA[i] = make_float2(0.f, 0.f);
        sB[i] = make_float2(0.f, 0.f);
    }

    const bool act = tid < NACT;
    const int  px  = tid / LREG;         // 0..19 (row pair)
    const int  py  = tid - px * LREG;    // 0..39 (column)
    const int  r0  = 2 * px;
    const int  gx0 = bX * TILE + r0 - HALO;   // even; row pair gx0, gx0+1
    const int  gy  = bY * TILE + py - HALO;

    const bool dom   = act && gx0 >= 0 && gx0 < NXg && gy >= 0 && gy < NYg;
    const bool inter = act && px >= 2 && px < 18 && py >= 4 && py < 36;
    const bool rim   = inter && (px < 4 || px >= 16 || py < 8 || py >= 32);

    const int o0 = SOFF(r0, py);
    const int o1 = o0 + SROW;
    const int goff0 = gx0 * GPitch + gy;
    const int oidx0 = gx0 * NYg + gy;

    // Per-point coefficients (exp+clip, folded with k), packed for f32x2 mixing.
    float2 PA0, PB0, PC0, PA1, PB1, PC1;
    float  cD0 = 0.f, cE0 = 0.f, cCq0 = 0.f, gs0 = 0.f;
    float  cD1 = 0.f, cE1 = 0.f, cCq1 = 0.f, gs1 = 0.f;
    PA0 = PB0 = PC0 = PA1 = PB1 = PC1 = make_float2(0.f, 0.f);
    if (dom) {
        #pragma unroll
        for (int i = 0; i < 2; ++i) {
            const int gi = (gx0 + i) * NYg + gy;
            const float C11 = clipf(expf(lc11[gi]), 5e10f, 2.5e11f) * K_COEF;
            const float C22 = clipf(expf(lc22[gi]), 5e9f,  5e10f)  * K_COEF;
            const float C12 = clipf(expf(lc12[gi]), 5e9f,  5e10f)  * K_COEF;
            const float C16 = clipf(expf(lc16[gi]), 0.0f,  6e10f)  * K_COEF;
            const float C26 = clipf(expf(lc26[gi]), 0.0f,  2e10f)  * K_COEF;
            const float C66 = clipf(expf(lc66[gi]), 5e9f,  3e10f)  * K_COEF;
            const float cCq = (C12 + C66) * 0.25f;
            const float2 PA = make_float2(C11, C66);          // d2x -> (Lx, Ly)
            const float2 PB = make_float2(C66, C22);          // d2y -> (Lx, Ly)
            const float2 PC = make_float2(C16 * 0.5f, C26 * 0.5f); // Dxy -> (Lx, Ly)
            const float  gg = gauss[gi] * K_SRC;
            if (i == 0) { PA0 = PA; PB0 = PB; PC0 = PC; cD0 = C16; cE0 = C26; cCq0 = cCq; gs0 = gg; }
            else        { PA1 = PA; PB1 = PB; PC1 = PC; cD1 = C16; cE1 = C26; cCq1 = cCq; gs1 = gg; }
        }
    }
    __syncthreads();   // smem zero + sig visible

    const float2 M2 = make_float2(-2.f, -2.f);
    const float2 N1 = make_float2(-1.f, -1.f);

    float2 c0 = make_float2(0.f, 0.f), c1 = make_float2(0.f, 0.f);
    float2 p0 = make_float2(0.f, 0.f), p1 = make_float2(0.f, 0.f);

    // One-point update (both components), packed math.
    auto pt = [&](float2 c, float2 u2, float2 vN, float2 vS, float2 vW, float2 vE,
                  float2 vNW, float2 vNE, float2 vSW, float2 vSE,
                  float2 PA, float2 PB, float2 PC,
                  float cD, float cE, float cCq, float gsv, float sigt) -> float2 {
        const float2 d2x = ffma2(c, M2, fadd2(vN, vS));
        const float2 d2y = ffma2(c, M2, fadd2(vW, vE));
        const float2 aa  = ffma2(vNE, N1, vNW);
        const float2 bb  = ffma2(vSE, N1, vSW);
        const float2 Dxy = ffma2(bb, N1, aa);
        const float2 L   = ffma2(Dxy, PC, ffma2(d2y, PB, fmul2(d2x, PA)));
        const float Lx = fmaf(cCq, Dxy.y, fmaf(cE, d2y.y, fmaf(cD, d2x.y, L.x)));
        float       Ly = fmaf(cCq, Dxy.x, fmaf(cE, d2y.x, fmaf(cD, d2x.x, L.y)));
        Ly = fmaf(sigt, gsv, Ly);
        return make_float2(fmaf(2.f, c.x, Lx) - u2.x,
                           fmaf(2.f, c.y, Ly) - u2.y);
    };

    auto substep = [&](const float2* __restrict__ src, float2* __restrict__ dst,
                       float sigt) {
        if (act) {
            // 10 neighbor loads; own-column interior rows come from registers.
            const float2 vAm = src[o0 - SROW - 1];
            const float2 vA0 = src[o0 - SROW];
            const float2 vAp = src[o0 - SROW + 1];
            const float2 vBm = src[o0 - 1];
            const float2 vBp = src[o0 + 1];
            const float2 vCm = src[o1 - 1];
            const float2 vCp = src[o1 + 1];
            const float2 vDm = src[o1 + SROW - 1];
            const float2 vD0 = src[o1 + SROW];
            const float2 vDp = src[o1 + SROW + 1];

            const float2 n0 = pt(c0, p0, vA0, c1, vBm, vBp, vAm, vAp, vCm, vCp,
                                 PA0, PB0, PC0, cD0, cE0, cCq0, gs0, sigt);
            const float2 n1 = pt(c1, p1, c0, vD0, vCm, vCp, vBm, vBp, vDm, vDp,
                                 PA1, PB1, PC1, cD1, cE1, cCq1, gs1, sigt);
            p0 = c0; c0 = n0;
            p1 = c1; c1 = n1;
            if (dom) { dst[o0] = n0; dst[o1] = n1; }
        }
        __syncthreads();
    };

    for (int ss = 0; ss < 48; ++ss) {
        const int t4 = ss * 4;
        substep(sA, sB, s_sig[t4 + 0]);
        substep(sB, sA, s_sig[t4 + 1]);
        substep(sA, sB, s_sig[t4 + 2]);
        substep(sB, sA, s_sig[t4 + 3]);
        // state (time T=4ss+4) now in sA; interior registers fresh.

        if (inter) {
            const int ob = ss * NPTS;
            out[ob + oidx0]            = c0.x;
            out[OUT_COMP + ob + oidx0] = c0.y;
            out[ob + oidx0 + NYg]            = c1.x;
            out[OUT_COMP + ob + oidx0 + NYg] = c1.y;
        }

        if (ss < 47) {
            if (rim) {
                __stcg(&g_G[goff0],          make_float4(c0.x, c0.y, p0.x, p0.y));
                __stcg(&g_G[goff0 + GPitch], make_float4(c1.x, c1.y, p1.x, p1.y));
            }
            grid_barrier(base + (unsigned)(ss + 1));
            if (dom && !inter) {
                const float4 h0 = __ldcg(&g_G[goff0]);
                const float4 h1 = __ldcg(&g_G[goff0 + GPitch]);
                c0 = make_float2(h0.x, h0.y); p0 = make_float2(h0.z, h0.w);
                c1 = make_float2(h1.x, h1.y); p1 = make_float2(h1.z, h1.w);
                sA[o0] = c0;
                sA[o1] = c1;
            }
            __syncthreads();   // halo smem writes visible before next substep
        }
    }
}

extern "C" void kernel_launch(void* const* d_in, const int* in_sizes, int n_in,
                              void* d_out, int out_size)
{
    const float* lc11  = (const float*)d_in[0];
    const float* lc12  = (const float*)d_in[1];
    const float* lc16  = (const float*)d_in[2];
    const float* lc22  = (const float*)d_in[3];
    const float* lc26  = (const float*)d_in[4];
    const float* lc66  = (const float*)d_in[5];
    const float* gauss = (const float*)d_in[6];
    const float* sig   = (const float*)d_in[7];
    float* out = (float*)d_out;

    aniso_wave_kernel<<<NBLOCKS, NTHREADS>>>(lc11, lc12, lc16, lc22, lc26, lc66,
                                             gauss, sig, out);
}

// round 12
// speedup vs baseline: 3.1403x; 1.4126x over previous
#include <cuda_runtime.h>
#include <cuda_bf16.h>

// Problem constants
#define NXg 384
#define NYg 384
#define NT  192
#define NPTS (NXg * NYg)          // 147456
#define NBLOCKS 144               // 12x12 tiles
#define NTHREADS 800              // 25 warps; all active (20 row-pairs x 40 cols)
#define TDIM 12
#define TILE 32
#define HALO 4
#define LREG 40                   // TILE + 2*HALO
#define SROW 44                   // smem row stride in float2
#define SMSZ (42 * SROW)
#define SOFF(r, c) (((r) + 1) * SROW + ((c) + 1))
#define GPitch 512
#define OUT_COMP (48 * NPTS)

// k = (dt^2 / rho) * (1/h^2) ; source uses dt^2/rho only
#define K_COEF  1.5527950310559006e-12f
#define K_SRC   1.5527950310559006e-20f

#define FLAG_STRIDE 32            // 128B per flag -> own L2 line

// Parity-double-buffered exchange: superstep ss writes g_GX[ss&1].
// Writer overwrite of parity p is licensed by its own consumption of the
// neighbors' parity-p data (happens-after neighbors consumed this writer's
// previous parity-p write) -> no global barrier needed.
__device__ float4 g_GA[NXg * GPitch];
__device__ float4 g_GB[NXg * GPitch];
// Per-block monotonic superstep flags (own L2 line each). Uniform at every
// launch boundary (each block advances exactly 47 per launch).
__device__ unsigned int g_flags[NBLOCKS * FLAG_STRIDE];

static __device__ __forceinline__ unsigned int ld_acq(const unsigned int* p)
{
    unsigned int v;
    asm volatile("ld.acquire.gpu.global.u32 %0, [%1];" : "=r"(v) : "l"(p) : "memory");
    return v;
}
static __device__ __forceinline__ void st_rel(unsigned int* p, unsigned int v)
{
    asm volatile("st.release.gpu.global.u32 [%0], %1;" :: "l"(p), "r"(v) : "memory");
}

// ---- packed f32x2 helpers (sm_100+) ----
static __device__ __forceinline__ float2 fadd2(float2 a, float2 b)
{
    unsigned long long ra = *reinterpret_cast<unsigned long long*>(&a);
    unsigned long long rb = *reinterpret_cast<unsigned long long*>(&b);
    unsigned long long rd;
    asm("add.rn.f32x2 %0, %1, %2;" : "=l"(rd) : "l"(ra), "l"(rb));
    float2 d; *reinterpret_cast<unsigned long long*>(&d) = rd; return d;
}
static __device__ __forceinline__ float2 fmul2(float2 a, float2 b)
{
    unsigned long long ra = *reinterpret_cast<unsigned long long*>(&a);
    unsigned long long rb = *reinterpret_cast<unsigned long long*>(&b);
    unsigned long long rd;
    asm("mul.rn.f32x2 %0, %1, %2;" : "=l"(rd) : "l"(ra), "l"(rb));
    float2 d; *reinterpret_cast<unsigned long long*>(&d) = rd; return d;
}
static __device__ __forceinline__ float2 ffma2(float2 a, float2 b, float2 c)
{
    unsigned long long ra = *reinterpret_cast<unsigned long long*>(&a);
    unsigned long long rb = *reinterpret_cast<unsigned long long*>(&b);
    unsigned long long rc = *reinterpret_cast<unsigned long long*>(&c);
    unsigned long long rd;
    asm("fma.rn.f32x2 %0, %1, %2, %3;" : "=l"(rd) : "l"(ra), "l"(rb), "l"(rc));
    float2 d; *reinterpret_cast<unsigned long long*>(&d) = rd; return d;
}

static __device__ __forceinline__ float clipf(float v, float lo, float hi)
{
    return fminf(fmaxf(v, lo), hi);
}

__global__ void __launch_bounds__(NTHREADS, 1)
aniso_wave_kernel(const float* __restrict__ lc11,
                  const float* __restrict__ lc12,
                  const float* __restrict__ lc16,
                  const float* __restrict__ lc22,
                  const float* __restrict__ lc26,
                  const float* __restrict__ lc66,
                  const float* __restrict__ gauss,
                  const float* __restrict__ sigg,
                  float* __restrict__ out)
{
    __shared__ float2 sA[SMSZ];
    __shared__ float2 sB[SMSZ];
    __shared__ float  s_sig[NT];

    const int tid = threadIdx.x;
    const int bX  = blockIdx.x / TDIM;
    const int bY  = blockIdx.x - bX * TDIM;

    if (tid < NT) s_sig[tid] = sigg[tid];

    // Launch-uniform flag base (every block advances exactly 47 per launch).
    const unsigned int base = ld_acq(&g_flags[blockIdx.x * FLAG_STRIDE]);

    for (int i = tid; i < SMSZ; i += NTHREADS) {
        sA[i] = make_float2(0.f, 0.f);
        sB[i] = make_float2(0.f, 0.f);
    }

    const int  px  = tid / LREG;         // 0..19 (row pair)
    const int  py  = tid - px * LREG;    // 0..39 (column)
    const int  r0  = 2 * px;
    const int  gx0 = bX * TILE + r0 - HALO;   // even; rows gx0, gx0+1
    const int  gy  = bY * TILE + py - HALO;

    const bool dom   = gx0 >= 0 && gx0 < NXg && gy >= 0 && gy < NYg;
    const bool inter = px >= 2 && px < 18 && py >= 4 && py < 36;
    const bool rim   = inter && (px < 4 || px >= 16 || py < 8 || py >= 32);
    const bool halo  = dom && !inter;

    const int o0 = SOFF(r0, py);
    const int o1 = o0 + SROW;
    const int goff0 = gx0 * GPitch + gy;
    const int oidx0 = gx0 * NYg + gy;

    // Halo points: the single source block that owns (gx0, gy).
    const unsigned int* src_flag = nullptr;
    if (halo) {
        const int sblk = (gx0 >> 5) * TDIM + (gy >> 5);
        src_flag = &g_flags[sblk * FLAG_STRIDE];
    }

    // Per-point coefficients (exp+clip, folded with k), packed for f32x2 mixing.
    float2 PA0, PB0, PC0, PA1, PB1, PC1;
    float  cD0 = 0.f, cE0 = 0.f, cCq0 = 0.f, gs0 = 0.f;
    float  cD1 = 0.f, cE1 = 0.f, cCq1 = 0.f, gs1 = 0.f;
    PA0 = PB0 = PC0 = PA1 = PB1 = PC1 = make_float2(0.f, 0.f);
    if (dom) {
        #pragma unroll
        for (int i = 0; i < 2; ++i) {
            const int gi = (gx0 + i) * NYg + gy;
            const float C11 = clipf(expf(lc11[gi]), 5e10f, 2.5e11f) * K_COEF;
            const float C22 = clipf(expf(lc22[gi]), 5e9f,  5e10f)  * K_COEF;
            const float C12 = clipf(expf(lc12[gi]), 5e9f,  5e10f)  * K_COEF;
            const float C16 = clipf(expf(lc16[gi]), 0.0f,  6e10f)  * K_COEF;
            const float C26 = clipf(expf(lc26[gi]), 0.0f,  2e10f)  * K_COEF;
            const float C66 = clipf(expf(lc66[gi]), 5e9f,  3e10f)  * K_COEF;
            const float cCq = (C12 + C66) * 0.25f;
            const float2 PA = make_float2(C11, C66);
            const float2 PB = make_float2(C66, C22);
            const float2 PC = make_float2(C16 * 0.5f, C26 * 0.5f);
            const float  gg = gauss[gi] * K_SRC;
            if (i == 0) { PA0 = PA; PB0 = PB; PC0 = PC; cD0 = C16; cE0 = C26; cCq0 = cCq; gs0 = gg; }
            else        { PA1 = PA; PB1 = PB; PC1 = PC; cD1 = C16; cE1 = C26; cCq1 = cCq; gs1 = gg; }
        }
    }
    __syncthreads();   // smem zero + sig visible

    const float2 M2 = make_float2(-2.f, -2.f);
    const float2 N1 = make_float2(-1.f, -1.f);

    float2 c0 = make_float2(0.f, 0.f), c1 = make_float2(0.f, 0.f);
    float2 p0 = make_float2(0.f, 0.f), p1 = make_float2(0.f, 0.f);

    auto pt = [&](float2 c, float2 u2, float2 vN, float2 vS, float2 vW, float2 vE,
                  float2 vNW, float2 vNE, float2 vSW, float2 vSE,
                  float2 PA, float2 PB, float2 PC,
                  float cD, float cE, float cCq, float gsv, float sigt) -> float2 {
        const float2 d2x = ffma2(c, M2, fadd2(vN, vS));
        const float2 d2y = ffma2(c, M2, fadd2(vW, vE));
        const float2 aa  = ffma2(vNE, N1, vNW);
        const float2 bb  = ffma2(vSE, N1, vSW);
        const float2 Dxy = ffma2(bb, N1, aa);
        const float2 L   = ffma2(Dxy, PC, ffma2(d2y, PB, fmul2(d2x, PA)));
        const float Lx = fmaf(cCq, Dxy.y, fmaf(cE, d2y.y, fmaf(cD, d2x.y, L.x)));
        float       Ly = fmaf(cCq, Dxy.x, fmaf(cE, d2y.x, fmaf(cD, d2x.x, L.y)));
        Ly = fmaf(sigt, gsv, Ly);
        return make_float2(fmaf(2.f, c.x, Lx) - u2.x,
                           fmaf(2.f, c.y, Ly) - u2.y);
    };

    auto substep = [&](const float2* __restrict__ src, float2* __restrict__ dst,
                       float sigt, bool dosync) {
        const float2 vAm = src[o0 - SROW - 1];
        const float2 vA0 = src[o0 - SROW];
        const float2 vAp = src[o0 - SROW + 1];
        const float2 vBm = src[o0 - 1];
        const float2 vBp = src[o0 + 1];
        const float2 vCm = src[o1 - 1];
        const float2 vCp = src[o1 + 1];
        const float2 vDm = src[o1 + SROW - 1];
        const float2 vD0 = src[o1 + SROW];
        const float2 vDp = src[o1 + SROW + 1];

        const float2 n0 = pt(c0, p0, vA0, c1, vBm, vBp, vAm, vAp, vCm, vCp,
                             PA0, PB0, PC0, cD0, cE0, cCq0, gs0, sigt);
        const float2 n1 = pt(c1, p1, c0, vD0, vCm, vCp, vBm, vBp, vDm, vDp,
                             PA1, PB1, PC1, cD1, cE1, cCq1, gs1, sigt);
        p0 = c0; c0 = n0;
        p1 = c1; c1 = n1;
        if (dom) { dst[o0] = n0; dst[o1] = n1; }
        if (dosync) __syncthreads();
    };

    for (int ss = 0; ss < 48; ++ss) {
        const int t4 = ss * 4;
        substep(sA, sB, s_sig[t4 + 0], true);
        substep(sB, sA, s_sig[t4 + 1], true);
        substep(sA, sB, s_sig[t4 + 2], true);
        substep(sB, sA, s_sig[t4 + 3], false);   // rim/out use registers only
        // state (time T = 4ss+4) in sA; interior registers fresh.

        if (ss < 47) {
            float4* gb = (ss & 1) ? g_GB : g_GA;

            if (rim) {
                __stcg(&gb[goff0],          make_float4(c0.x, c0.y, p0.x, p0.y));
                __stcg(&gb[goff0 + GPitch], make_float4(c1.x, c1.y, p1.x, p1.y));
            }
            __syncthreads();                       // rim stores before flag
            if (tid == 0)
                st_rel(&g_flags[blockIdx.x * FLAG_STRIDE], base + (unsigned)(ss + 1));

            if (inter) {                           // snapshot overlaps neighbor sync
                const int ob = ss * NPTS;
                out[ob + oidx0]                  = c0.x;
                out[OUT_COMP + ob + oidx0]       = c0.y;
                out[ob + oidx0 + NYg]            = c1.x;
                out[OUT_COMP + ob + oidx0 + NYg] = c1.y;
            }

            if (halo) {                            // wait only on OUR source block
                const unsigned int target = base + (unsigned)(ss + 1);
                while (ld_acq(src_flag) < target) { }
                const float4 h0 = __ldcg(&gb[goff0]);
                const float4 h1 = __ldcg(&gb[goff0 + GPitch]);
                c0 = make_float2(h0.x, h0.y); p0 = make_float2(h0.z, h0.w);
                c1 = make_float2(h1.x, h1.y); p1 = make_float2(h1.z, h1.w);
                sA[o0] = c0;
                sA[o1] = c1;
            }
            __syncthreads();                       // halo smem visible for next substep
        } else {
            if (inter) {
                const int ob = ss * NPTS;
                out[ob + oidx0]                  = c0.x;
                out[OUT_COMP + ob + oidx0]       = c0.y;
                out[ob + oidx0 + NYg]            = c1.x;
                out[OUT_COMP + ob + oidx0 + NYg] = c1.y;
            }
        }
    }
}

extern "C" void kernel_launch(void* const* d_in, const int* in_sizes, int n_in,
                              void* d_out, int out_size)
{
    const float* lc11  = (const float*)d_in[0];
    const float* lc12  = (const float*)d_in[1];
    const float* lc16  = (const float*)d_in[2];
    const float* lc22  = (const float*)d_in[3];
    const float* lc26  = (const float*)d_in[4];
    const float* lc66  = (const float*)d_in[5];
    const float* gauss = (const float*)d_in[6];
    const float* sig   = (const float*)d_in[7];
    float* out = (float*)d_out;

    aniso_wave_kernel<<<NBLOCKS, NTHREADS>>>(lc11, lc12, lc16, lc22, lc26, lc66,
                                             gauss, sig, out);
}

// round 14
// speedup vs baseline: 3.3267x; 1.0594x over previous
#include <cuda_runtime.h>
#include <cuda_bf16.h>

// Problem constants
#define NXg 384
#define NYg 384
#define NT  192
#define NPTS (NXg * NYg)          // 147456
#define TDIMX 24                  // tiles in x (16 rows each)
#define TDIMY 12                  // tiles in y (32 cols each)
#define NBLOCKS (TDIMX * TDIMY)   // 288 -> 2 CTAs per SM
#define NTHREADS 480              // 15 warps; 12 row-pairs x 40 cols
#define TILEX 16
#define TILEY 32
#define HALO 4
#define LREGX 24                  // TILEX + 2*HALO local rows
#define LREGY 40                  // TILEY + 2*HALO local cols
#define SROW 44                   // smem row stride in float2
#define SMSZ (26 * SROW)          // 26 rows (1 pad each side) x 44
#define SOFF(r, c) (((r) + 1) * SROW + ((c) + 1))
#define GPitch 512
#define OUT_COMP (48 * NPTS)

// k = (dt^2 / rho) * (1/h^2) ; source uses dt^2/rho only
#define K_COEF  1.5527950310559006e-12f
#define K_SRC   1.5527950310559006e-20f

#define FLAG_STRIDE 32            // 128B per flag -> own L2 line

// Parity-double-buffered exchange (global coords). Writer overwrite of parity
// p is licensed by its own consumption of neighbors' parity-p data.
__device__ float4 g_GA[NXg * GPitch];
__device__ float4 g_GB[NXg * GPitch];
// Per-block monotonic superstep flags (own L2 line each). Uniform at launch
// boundaries (each block advances exactly 47 per launch).
__device__ unsigned int g_flags[NBLOCKS * FLAG_STRIDE];

static __device__ __forceinline__ unsigned int ld_acq(const unsigned int* p)
{
    unsigned int v;
    asm volatile("ld.acquire.gpu.global.u32 %0, [%1];" : "=r"(v) : "l"(p) : "memory");
    return v;
}
static __device__ __forceinline__ void st_rel(unsigned int* p, unsigned int v)
{
    asm volatile("st.release.gpu.global.u32 [%0], %1;" :: "l"(p), "r"(v) : "memory");
}

// ---- packed f32x2 helpers (sm_100+) ----
static __device__ __forceinline__ float2 fadd2(float2 a, float2 b)
{
    unsigned long long ra = *reinterpret_cast<unsigned long long*>(&a);
    unsigned long long rb = *reinterpret_cast<unsigned long long*>(&b);
    unsigned long long rd;
    asm("add.rn.f32x2 %0, %1, %2;" : "=l"(rd) : "l"(ra), "l"(rb));
    float2 d; *reinterpret_cast<unsigned long long*>(&d) = rd; return d;
}
static __device__ __forceinline__ float2 fmul2(float2 a, float2 b)
{
    unsigned long long ra = *reinterpret_cast<unsigned long long*>(&a);
    unsigned long long rb = *reinterpret_cast<unsigned long long*>(&b);
    unsigned long long rd;
    asm("mul.rn.f32x2 %0, %1, %2;" : "=l"(rd) : "l"(ra), "l"(rb));
    float2 d; *reinterpret_cast<unsigned long long*>(&d) = rd; return d;
}
static __device__ __forceinline__ float2 ffma2(float2 a, float2 b, float2 c)
{
    unsigned long long ra = *reinterpret_cast<unsigned long long*>(&a);
    unsigned long long rb = *reinterpret_cast<unsigned long long*>(&b);
    unsigned long long rc = *reinterpret_cast<unsigned long long*>(&c);
    unsigned long long rd;
    asm("fma.rn.f32x2 %0, %1, %2, %3;" : "=l"(rd) : "l"(ra), "l"(rb), "l"(rc));
    float2 d; *reinterpret_cast<unsigned long long*>(&d) = rd; return d;
}

static __device__ __forceinline__ float clipf(float v, float lo, float hi)
{
    return fminf(fmaxf(v, lo), hi);
}

__global__ void __launch_bounds__(NTHREADS, 2)
aniso_wave_kernel(const float* __restrict__ lc11,
                  const float* __restrict__ lc12,
                  const float* __restrict__ lc16,
                  const float* __restrict__ lc22,
                  const float* __restrict__ lc26,
                  const float* __restrict__ lc66,
                  const float* __restrict__ gauss,
                  const float* __restrict__ sigg,
                  float* __restrict__ out)
{
    __shared__ float2 sA[SMSZ];
    __shared__ float2 sB[SMSZ];
    __shared__ float  s_sig[NT];

    const int tid = threadIdx.x;
    const int bX  = blockIdx.x / TDIMY;
    const int bY  = blockIdx.x - bX * TDIMY;

    if (tid < NT) s_sig[tid] = sigg[tid];

    // Launch-uniform flag base (every block advances exactly 47 per launch).
    const unsigned int base = ld_acq(&g_flags[blockIdx.x * FLAG_STRIDE]);

    for (int i = tid; i < SMSZ; i += NTHREADS) {
        sA[i] = make_float2(0.f, 0.f);
        sB[i] = make_float2(0.f, 0.f);
    }

    const int  px  = tid / LREGY;        // 0..11 (row pair)
    const int  py  = tid - px * LREGY;   // 0..39 (column)
    const int  r0  = 2 * px;
    const int  gx0 = bX * TILEX + r0 - HALO;   // even; rows gx0, gx0+1
    const int  gy  = bY * TILEY + py - HALO;

    const bool dom   = gx0 >= 0 && gx0 < NXg && gy >= 0 && gy < NYg;
    const bool inter = px >= 2 && px < 10 && py >= 4 && py < 36;
    const bool rim   = inter && (px < 4 || px >= 8 || py < 8 || py >= 32);
    const bool halo  = dom && !inter;

    const int o0 = SOFF(r0, py);
    const int o1 = o0 + SROW;
    const int goff0 = gx0 * GPitch + gy;
    const int oidx0 = gx0 * NYg + gy;

    // Halo points: single source block owning (gx0, gy). Row pair never
    // straddles a 16-row tile boundary (gx0 even).
    const unsigned int* src_flag = nullptr;
    if (halo) {
        const int sblk = (gx0 >> 4) * TDIMY + (gy >> 5);
        src_flag = &g_flags[sblk * FLAG_STRIDE];
    }

    // Per-point coefficients (exp+clip, folded with k), packed for f32x2 mixing.
    float2 PA0, PB0, PC0, PA1, PB1, PC1;
    float  cD0 = 0.f, cE0 = 0.f, cCq0 = 0.f, gs0 = 0.f;
    float  cD1 = 0.f, cE1 = 0.f, cCq1 = 0.f, gs1 = 0.f;
    PA0 = PB0 = PC0 = PA1 = PB1 = PC1 = make_float2(0.f, 0.f);
    if (dom) {
        #pragma unroll
        for (int i = 0; i < 2; ++i) {
            const int gi = (gx0 + i) * NYg + gy;
            const float C11 = clipf(expf(lc11[gi]), 5e10f, 2.5e11f) * K_COEF;
            const float C22 = clipf(expf(lc22[gi]), 5e9f,  5e10f)  * K_COEF;
            const float C12 = clipf(expf(lc12[gi]), 5e9f,  5e10f)  * K_COEF;
            const float C16 = clipf(expf(lc16[gi]), 0.0f,  6e10f)  * K_COEF;
            const float C26 = clipf(expf(lc26[gi]), 0.0f,  2e10f)  * K_COEF;
            const float C66 = clipf(expf(lc66[gi]), 5e9f,  3e10f)  * K_COEF;
            const float cCq = (C12 + C66) * 0.25f;
            const float2 PA = make_float2(C11, C66);
            const float2 PB = make_float2(C66, C22);
            const float2 PC = make_float2(C16 * 0.5f, C26 * 0.5f);
            const float  gg = gauss[gi] * K_SRC;
            if (i == 0) { PA0 = PA; PB0 = PB; PC0 = PC; cD0 = C16; cE0 = C26; cCq0 = cCq; gs0 = gg; }
            else        { PA1 = PA; PB1 = PB; PC1 = PC; cD1 = C16; cE1 = C26; cCq1 = cCq; gs1 = gg; }
        }
    }
    __syncthreads();   // smem zero + sig visible

    const float2 M2 = make_float2(-2.f, -2.f);
    const float2 N1 = make_float2(-1.f, -1.f);

    float2 c0 = make_float2(0.f, 0.f), c1 = make_float2(0.f, 0.f);
    float2 p0 = make_float2(0.f, 0.f), p1 = make_float2(0.f, 0.f);

    auto pt = [&](float2 c, float2 u2, float2 vN, float2 vS, float2 vW, float2 vE,
                  float2 vNW, float2 vNE, float2 vSW, float2 vSE,
                  float2 PA, float2 PB, float2 PC,
                  float cD, float cE, float cCq, float gsv, float sigt) -> float2 {
        const float2 d2x = ffma2(c, M2, fadd2(vN, vS));
        const float2 d2y = ffma2(c, M2, fadd2(vW, vE));
        const float2 aa  = ffma2(vNE, N1, vNW);
        const float2 bb  = ffma2(vSE, N1, vSW);
        const float2 Dxy = ffma2(bb, N1, aa);
        const float2 L   = ffma2(Dxy, PC, ffma2(d2y, PB, fmul2(d2x, PA)));
        const float Lx = fmaf(cCq, Dxy.y, fmaf(cE, d2y.y, fmaf(cD, d2x.y, L.x)));
        float       Ly = fmaf(cCq, Dxy.x, fmaf(cE, d2y.x, fmaf(cD, d2x.x, L.y)));
        Ly = fmaf(sigt, gsv, Ly);
        return make_float2(fmaf(2.f, c.x, Lx) - u2.x,
                           fmaf(2.f, c.y, Ly) - u2.y);
    };

    auto substep = [&](const float2* __restrict__ src, float2* __restrict__ dst,
                       float sigt, bool dosync) {
        const float2 vAm = src[o0 - SROW - 1];
        const float2 vA0 = src[o0 - SROW];
        const float2 vAp = src[o0 - SROW + 1];
        const float2 vBm = src[o0 - 1];
        const float2 vBp = src[o0 + 1];
        const float2 vCm = src[o1 - 1];
        const float2 vCp = src[o1 + 1];
        const float2 vDm = src[o1 + SROW - 1];
        const float2 vD0 = src[o1 + SROW];
        const float2 vDp = src[o1 + SROW + 1];

        const float2 n0 = pt(c0, p0, vA0, c1, vBm, vBp, vAm, vAp, vCm, vCp,
                             PA0, PB0, PC0, cD0, cE0, cCq0, gs0, sigt);
        const float2 n1 = pt(c1, p1, c0, vD0, vCm, vCp, vBm, vBp, vDm, vDp,
                             PA1, PB1, PC1, cD1, cE1, cCq1, gs1, sigt);
        p0 = c0; c0 = n0;
        p1 = c1; c1 = n1;
        if (dom) { dst[o0] = n0; dst[o1] = n1; }
        if (dosync) __syncthreads();
    };

    for (int ss = 0; ss < 48; ++ss) {
        const int t4 = ss * 4;
        substep(sA, sB, s_sig[t4 + 0], true);
        substep(sB, sA, s_sig[t4 + 1], true);
        substep(sA, sB, s_sig[t4 + 2], true);
        substep(sB, sA, s_sig[t4 + 3], false);   // rim/out use registers only
        // state (time T = 4ss+4) in sA; interior registers fresh.

        if (ss < 47) {
            float4* gb = (ss & 1) ? g_GB : g_GA;

            if (rim) {
                __stcg(&gb[goff0],          make_float4(c0.x, c0.y, p0.x, p0.y));
                __stcg(&gb[goff0 + GPitch], make_float4(c1.x, c1.y, p1.x, p1.y));
            }
            __syncthreads();                       // rim stores before flag
            if (tid == 0)
                st_rel(&g_flags[blockIdx.x * FLAG_STRIDE], base + (unsigned)(ss + 1));

            if (inter) {                           // snapshot overlaps neighbor sync
                const int ob = ss * NPTS;
                out[ob + oidx0]                  = c0.x;
                out[OUT_COMP + ob + oidx0]       = c0.y;
                out[ob + oidx0 + NYg]            = c1.x;
                out[OUT_COMP + ob + oidx0 + NYg] = c1.y;
            }

            if (halo) {                            // wait only on OUR source block
                const unsigned int target = base + (unsigned)(ss + 1);
                while (ld_acq(src_flag) < target) { }
                const float4 h0 = __ldcg(&gb[goff0]);
                const float4 h1 = __ldcg(&gb[goff0 + GPitch]);
                c0 = make_float2(h0.x, h0.y); p0 = make_float2(h0.z, h0.w);
                c1 = make_float2(h1.x, h1.y); p1 = make_float2(h1.z, h1.w);
                sA[o0] = c0;
                sA[o1] = c1;
            }
            __syncthreads();                       // halo smem visible for next substep
        } else {
            if (inter) {
                const int ob = ss * NPTS;
                out[ob + oidx0]                  = c0.x;
                out[OUT_COMP + ob + oidx0]       = c0.y;
                out[ob + oidx0 + NYg]            = c1.x;
                out[OUT_COMP + ob + oidx0 + NYg] = c1.y;
            }
        }
    }
}

extern "C" void kernel_launch(void* const* d_in, const int* in_sizes, int n_in,
                              void* d_out, int out_size)
{
    const float* lc11  = (const float*)d_in[0];
    const float* lc12  = (const float*)d_in[1];
    const float* lc16  = (const float*)d_in[2];
    const float* lc22  = (const float*)d_in[3];
    const float* lc26  = (const float*)d_in[4];
    const float* lc66  = (const float*)d_in[5];
    const float* gauss = (const float*)d_in[6];
    const float* sig   = (const float*)d_in[7];
    float* out = (float*)d_out;

    aniso_wave_kernel<<<NBLOCKS, NTHREADS>>>(lc11, lc12, lc16, lc22, lc26, lc66,
                                             gauss, sig, out);
}

// round 16
// speedup vs baseline: 3.4940x; 1.0503x over previous
#include <cuda_runtime.h>
#include <cuda_bf16.h>

// Problem constants
#define NXg 384
#define NYg 384
#define NT  192
#define NPTS (NXg * NYg)          // 147456
#define TDIMX 24                  // tiles in x (16 rows each)
#define TDIMY 12                  // tiles in y (32 cols each)
#define NBLOCKS (TDIMX * TDIMY)   // 288 -> 2 CTAs per SM
#define NTHREADS 256              // 8 warps; 240 active quad-owners
#define NQUAD 240                 // 12 x 20 quads (2x2 points each)
#define TILEX 16
#define TILEY 32
#define HALO 4
#define LREGY 40
#define SROW 44                   // smem row stride in float2 (even -> 16B rows)
#define SMSZ (26 * SROW)
#define SOFF(r, c) (((r) + 1) * SROW + ((c) + 1))
#define GPitch 512
#define OUT_COMP (48 * NPTS)

#define K_COEF  1.5527950310559006e-12f
#define K_SRC   1.5527950310559006e-20f

#define FLAG_STRIDE 32            // 128B per flag -> own L2 line

// Parity-double-buffered exchange (global coords). Writer overwrite of parity
// p is licensed by its own consumption of neighbors' parity-p data.
__device__ float4 g_GA[NXg * GPitch];
__device__ float4 g_GB[NXg * GPitch];
// Per-block monotonic superstep flags (own L2 line each); uniform at launch
// boundaries (each block advances exactly 47 per launch).
__device__ unsigned int g_flags[NBLOCKS * FLAG_STRIDE];

static __device__ __forceinline__ unsigned int ld_acq(const unsigned int* p)
{
    unsigned int v;
    asm volatile("ld.acquire.gpu.global.u32 %0, [%1];" : "=r"(v) : "l"(p) : "memory");
    return v;
}
static __device__ __forceinline__ void st_rel(unsigned int* p, unsigned int v)
{
    asm volatile("st.release.gpu.global.u32 [%0], %1;" :: "l"(p), "r"(v) : "memory");
}

// ---- packed f32x2 helpers (sm_100+) ----
static __device__ __forceinline__ float2 fadd2(float2 a, float2 b)
{
    unsigned long long ra = *reinterpret_cast<unsigned long long*>(&a);
    unsigned long long rb = *reinterpret_cast<unsigned long long*>(&b);
    unsigned long long rd;
    asm("add.rn.f32x2 %0, %1, %2;" : "=l"(rd) : "l"(ra), "l"(rb));
    float2 d; *reinterpret_cast<unsigned long long*>(&d) = rd; return d;
}
static __device__ __forceinline__ float2 fmul2(float2 a, float2 b)
{
    unsigned long long ra = *reinterpret_cast<unsigned long long*>(&a);
    unsigned long long rb = *reinterpret_cast<unsigned long long*>(&b);
    unsigned long long rd;
    asm("mul.rn.f32x2 %0, %1, %2;" : "=l"(rd) : "l"(ra), "l"(rb));
    float2 d; *reinterpret_cast<unsigned long long*>(&d) = rd; return d;
}
static __device__ __forceinline__ float2 ffma2(float2 a, float2 b, float2 c)
{
    unsigned long long ra = *reinterpret_cast<unsigned long long*>(&a);
    unsigned long long rb = *reinterpret_cast<unsigned long long*>(&b);
    unsigned long long rc = *reinterpret_cast<unsigned long long*>(&c);
    unsigned long long rd;
    asm("fma.rn.f32x2 %0, %1, %2, %3;" : "=l"(rd) : "l"(ra), "l"(rb), "l"(rc));
    float2 d; *reinterpret_cast<unsigned long long*>(&d) = rd; return d;
}

static __device__ __forceinline__ float clipf(float v, float lo, float hi)
{
    return fminf(fmaxf(v, lo), hi);
}

__global__ void __launch_bounds__(NTHREADS, 2)
aniso_wave_kernel(const float* __restrict__ lc11,
                  const float* __restrict__ lc12,
                  const float* __restrict__ lc16,
                  const float* __restrict__ lc22,
                  const float* __restrict__ lc26,
                  const float* __restrict__ lc66,
                  const float* __restrict__ gauss,
                  const float* __restrict__ sigg,
                  float* __restrict__ out)
{
    __shared__ float2 sA[SMSZ];
    __shared__ float2 sB[SMSZ];
    __shared__ float  s_sig[NT];

    const int tid = threadIdx.x;
    const int bX  = blockIdx.x / TDIMY;
    const int bY  = blockIdx.x - bX * TDIMY;

    if (tid < NT) s_sig[tid] = sigg[tid];

    const unsigned int base = ld_acq(&g_flags[blockIdx.x * FLAG_STRIDE]);

    for (int i = tid; i < SMSZ; i += NTHREADS) {
        sA[i] = make_float2(0.f, 0.f);
        sB[i] = make_float2(0.f, 0.f);
    }

    const bool act = tid < NQUAD;
    const int  q   = act ? tid : 0;
    const int  qx  = q / 20;            // 0..11 : rows 2qx, 2qx+1
    const int  qy  = q - qx * 20;       // 0..19 : cols 2qy, 2qy+1
    const int  r   = 2 * qx;            // local row (even)
    const int  c   = 2 * qy;            // local col (even)
    const int  gx0 = bX * TILEX + r - HALO;   // even
    const int  gy0 = bY * TILEY + c - HALO;   // even

    const bool dom   = act && gx0 >= 0 && gx0 < NXg && gy0 >= 0 && gy0 < NYg;
    const bool inter = act && qx >= 2 && qx < 10 && qy >= 2 && qy < 18;
    const bool rim   = inter && (qx < 4 || qx >= 8 || qy < 4 || qy >= 16);
    const bool halo  = dom && !inter;

    // smem anchors. Quad cols even => (c) index even in smem (+1 layout shift
    // puts col c-1 at even float2 index) -> 16B-aligned float4 loads.
    const int oT = SOFF(r - 1, c - 1);  // row r-1, col c-1  (even index)
    const int o0 = SOFF(r,     c - 1);  // row r
    const int o1 = SOFF(r + 1, c - 1);  // row r+1
    const int oS = SOFF(r + 2, c - 1);  // row r+2
    const int ow = SOFF(r, c);          // own (r,c)

    const int goff  = gx0 * GPitch + gy0;
    const int oidx  = gx0 * NYg + gy0;

    const unsigned int* src_flag = nullptr;
    if (halo) {
        const int sblk = (gx0 >> 4) * TDIMY + (gy0 >> 5);
        src_flag = &g_flags[sblk * FLAG_STRIDE];
    }

    // Per-point coefficients for the 4 quad points (i*2+j : row i, col j).
    float2 PA[4], PB[4], PC[4];
    float  cD[4], cE[4], cCq[4], gs[4];
    #pragma unroll
    for (int p = 0; p < 4; ++p) {
        PA[p] = PB[p] = PC[p] = make_float2(0.f, 0.f);
        cD[p] = cE[p] = cCq[p] = gs[p] = 0.f;
    }
    if (dom) {
        #pragma unroll
        for (int i = 0; i < 2; ++i)
        #pragma unroll
        for (int j = 0; j < 2; ++j) {
            const int p  = i * 2 + j;
            const int gi = (gx0 + i) * NYg + (gy0 + j);
            const float C11 = clipf(expf(lc11[gi]), 5e10f, 2.5e11f) * K_COEF;
            const float C22 = clipf(expf(lc22[gi]), 5e9f,  5e10f)  * K_COEF;
            const float C12 = clipf(expf(lc12[gi]), 5e9f,  5e10f)  * K_COEF;
            const float C16 = clipf(expf(lc16[gi]), 0.0f,  6e10f)  * K_COEF;
            const float C26 = clipf(expf(lc26[gi]), 0.0f,  2e10f)  * K_COEF;
            const float C66 = clipf(expf(lc66[gi]), 5e9f,  3e10f)  * K_COEF;
            PA[p]  = make_float2(C11, C66);
            PB[p]  = make_float2(C66, C22);
            PC[p]  = make_float2(C16 * 0.5f, C26 * 0.5f);
            cD[p]  = C16; cE[p] = C26;
            cCq[p] = (C12 + C66) * 0.25f;
            gs[p]  = gauss[gi] * K_SRC;
        }
    }
    __syncthreads();   // smem zero + sig visible

    const float2 M2 = make_float2(-2.f, -2.f);
    const float2 N1 = make_float2(-1.f, -1.f);

    float2 cc0 = make_float2(0.f, 0.f), cc1 = cc0, cc2 = cc0, cc3 = cc0;
    float2 pp0 = cc0, pp1 = cc0, pp2 = cc0, pp3 = cc0;

    auto pt = [&](float2 ctr, float2 u2, float2 vN, float2 vS, float2 vW, float2 vE,
                  float2 vNW, float2 vNE, float2 vSW, float2 vSE,
                  int p, float sigt) -> float2 {
        const float2 d2x = ffma2(ctr, M2, fadd2(vN, vS));
        const float2 d2y = ffma2(ctr, M2, fadd2(vW, vE));
        const float2 aa  = ffma2(vNE, N1, vNW);
        const float2 bb  = ffma2(vSE, N1, vSW);
        const float2 Dxy = ffma2(bb, N1, aa);
        const float2 L   = ffma2(Dxy, PC[p], ffma2(d2y, PB[p], fmul2(d2x, PA[p])));
        const float Lx = fmaf(cCq[p], Dxy.y, fmaf(cE[p], d2y.y, fmaf(cD[p], d2x.y, L.x)));
        float       Ly = fmaf(cCq[p], Dxy.x, fmaf(cE[p], d2y.x, fmaf(cD[p], d2x.x, L.y)));
        Ly = fmaf(sigt, gs[p], Ly);
        return make_float2(fmaf(2.f, ctr.x, Lx) - u2.x,
                           fmaf(2.f, ctr.y, Ly) - u2.y);
    };

    auto substep = [&](const float2* __restrict__ src, float2* __restrict__ dst,
                       float sigt, bool dosync) {
        // 8 aligned LDS.128: rows r-1, r, r+1, r+2, cols [c-1,c] and [c+1,c+2]
        const float4 Ta = *reinterpret_cast<const float4*>(src + oT);
        const float4 Tb = *reinterpret_cast<const float4*>(src + oT + 2);
        const float4 Aa = *reinterpret_cast<const float4*>(src + o0);
        const float4 Ab = *reinterpret_cast<const float4*>(src + o0 + 2);
        const float4 Ba = *reinterpret_cast<const float4*>(src + o1);
        const float4 Bb = *reinterpret_cast<const float4*>(src + o1 + 2);
        const float4 Sa = *reinterpret_cast<const float4*>(src + oS);
        const float4 Sb = *reinterpret_cast<const float4*>(src + oS + 2);

        // 4x4 float2 neighborhood; centers from registers.
        const float2 V00 = make_float2(Ta.x, Ta.y), V01 = make_float2(Ta.z, Ta.w);
        const float2 V02 = make_float2(Tb.x, Tb.y), V03 = make_float2(Tb.z, Tb.w);
        const float2 V10 = make_float2(Aa.x, Aa.y), V13 = make_float2(Ab.z, Ab.w);
        const float2 V20 = make_float2(Ba.x, Ba.y), V23 = make_float2(Bb.z, Bb.w);
        const float2 V30 = make_float2(Sa.x, Sa.y), V31 = make_float2(Sa.z, Sa.w);
        const float2 V32 = make_float2(Sb.x, Sb.y), V33 = make_float2(Sb.z, Sb.w);

        const float2 n0 = pt(cc0, pp0, V01, cc2, V10, cc1, V00, V02, V20, cc3, 0, sigt);
        const float2 n1 = pt(cc1, pp1, V02, cc3, cc0, V13, V01, V03, cc2, V23, 1, sigt);
        const float2 n2 = pt(cc2, pp2, cc0, V31, V20, cc3, V10, cc1, V30, V32, 2, sigt);
        const float2 n3 = pt(cc3, pp3, cc1, V32, cc2, V23, cc0, V13, V31, V33, 3, sigt);

        pp0 = cc0; cc0 = n0;
        pp1 = cc1; cc1 = n1;
        pp2 = cc2; cc2 = n2;
        pp3 = cc3; cc3 = n3;
        if (dom) {
            dst[ow]            = n0;
            dst[ow + 1]        = n1;
            dst[ow + SROW]     = n2;
            dst[ow + SROW + 1] = n3;
        }
        if (dosync) __syncthreads();
    };

    for (int ss = 0; ss < 48; ++ss) {
        const int t4 = ss * 4;
        substep(sA, sB, s_sig[t4 + 0], true);
        substep(sB, sA, s_sig[t4 + 1], true);
        substep(sA, sB, s_sig[t4 + 2], true);
        substep(sB, sA, s_sig[t4 + 3], false);   // rim/out use registers only
        // state (time T = 4ss+4) in sA; interior registers fresh.

        if (ss < 47) {
            float4* gb = (ss & 1) ? g_GB : g_GA;

            if (rim) {
                __stcg(&gb[goff],              make_float4(cc0.x, cc0.y, pp0.x, pp0.y));
                __stcg(&gb[goff + 1],          make_float4(cc1.x, cc1.y, pp1.x, pp1.y));
                __stcg(&gb[goff + GPitch],     make_float4(cc2.x, cc2.y, pp2.x, pp2.y));
                __stcg(&gb[goff + GPitch + 1], make_float4(cc3.x, cc3.y, pp3.x, pp3.y));
            }
            __syncthreads();                       // rim stores before flag
            if (tid == 0)
                st_rel(&g_flags[blockIdx.x * FLAG_STRIDE], base + (unsigned)(ss + 1));

            if (inter) {                           // snapshot overlaps neighbor sync
                const int ob = ss * NPTS + oidx;
                *reinterpret_cast<float2*>(out + ob)
                    = make_float2(cc0.x, cc1.x);
                *reinterpret_cast<float2*>(out + ob + NYg)
                    = make_float2(cc2.x, cc3.x);
                *reinterpret_cast<float2*>(out + OUT_COMP + ob)
                    = make_float2(cc0.y, cc1.y);
                *reinterpret_cast<float2*>(out + OUT_COMP + ob + NYg)
                    = make_float2(cc2.y, cc3.y);
            }

            if (halo) {                            // wait only on OUR source block
                const unsigned int target = base + (unsigned)(ss + 1);
                while (ld_acq(src_flag) < target) { }
                const float4 h0 = __ldcg(&gb[goff]);
                const float4 h1 = __ldcg(&gb[goff + 1]);
                const float4 h2 = __ldcg(&gb[goff + GPitch]);
                const float4 h3 = __ldcg(&gb[goff + GPitch + 1]);
                cc0 = make_float2(h0.x, h0.y); pp0 = make_float2(h0.z, h0.w);
                cc1 = make_float2(h1.x, h1.y); pp1 = make_float2(h1.z, h1.w);
                cc2 = make_float2(h2.x, h2.y); pp2 = make_float2(h2.z, h2.w);
                cc3 = make_float2(h3.x, h3.y); pp3 = make_float2(h3.z, h3.w);
                sA[ow]            = cc0;
                sA[ow + 1]        = cc1;
                sA[ow + SROW]     = cc2;
                sA[ow + SROW + 1] = cc3;
            }
            __syncthreads();                       // halo smem visible for next substep
        } else {
            if (inter) {
                const int ob = ss * NPTS + oidx;
                *reinterpret_cast<float2*>(out + ob)
                    = make_float2(cc0.x, cc1.x);
                *reinterpret_cast<float2*>(out + ob + NYg)
                    = make_float2(cc2.x, cc3.x);
                *reinterpret_cast<float2*>(out + OUT_COMP + ob)
                    = make_float2(cc0.y, cc1.y);
                *reinterpret_cast<float2*>(out + OUT_COMP + ob + NYg)
                    = make_float2(cc2.y, cc3.y);
            }
        }
    }
}

extern "C" void kernel_launch(void* const* d_in, const int* in_sizes, int n_in,
                              void* d_out, int out_size)
{
    const float* lc11  = (const float*)d_in[0];
    const float* lc12  = (const float*)d_in[1];
    const float* lc16  = (const float*)d_in[2];
    const float* lc22  = (const float*)d_in[3];
    const float* lc26  = (const float*)d_in[4];
    const float* lc66  = (const float*)d_in[5];
    const float* gauss = (const float*)d_in[6];
    const float* sig   = (const float*)d_in[7];
    float* out = (float*)d_out;

    aniso_wave_kernel<<<NBLOCKS, NTHREADS>>>(lc11, lc12, lc16, lc22, lc26, lc66,
                                             gauss, sig, out);
}